// round 5
// baseline (speedup 1.0000x reference)
#include <cuda_runtime.h>
#include <cuda_bf16.h>
#include <cstdint>

// ---------------------------------------------------------------------------
// GatingNetwork: logits = x @ W^T + b ; softmax ; top-2 (values, indices)
// x: [16384, 4096] f32, W: [64, 4096] f32, b: [64] f32
// out: [0..32768) = top2 values, [32768..65536) = top2 indices (as float)
//
// 2-way bf16 split of both operands, 3 partial products (HH+HM+MH) on
// mma.sync m16n8k16 -> logit abs error ~1e-6. Tokens whose top-3 logit gaps
// are < GAP_THR are flagged and recomputed exactly in fp32 by a fixup kernel
// (deterministic correctness, negligible cost).
// ---------------------------------------------------------------------------

#define HIDDEN   4096
#define NEXP     64
#define NTOK     16384
#define MTILE    128
#define NCTA     (NTOK / MTILE)        // 128
#define THREADS  512
#define NSTEP    (HIDDEN / 16)         // 256 k16-steps
#define STEPS_PER_CHUNK 8              // K=128 per W chunk
#define NCHUNK   (NSTEP / STEPS_PER_CHUNK)  // 32
#define GAP_THR  2e-4f

// W fragment image: per k16 step: 4 mblocks x 2 splits x 32 lanes x uint4
#define FRAG_PER_STEP   (4 * 2 * 32)           // 256 uint4 = 4 KB
#define CHUNK_BYTES     (STEPS_PER_CHUNK * FRAG_PER_STEP * 16)  // 32768
#define SMEM_TOTAL      (3 * CHUNK_BYTES)      // 98304

__device__ uint4 g_Wfrag[NSTEP * FRAG_PER_STEP];   // 1 MB
__device__ int   g_flag_count;
__device__ int   g_flag_tokens[NTOK];

static __device__ __forceinline__ uint32_t s2u(const void* p) {
    uint32_t a;
    asm("{ .reg .u64 t; cvta.to.shared.u64 t, %1; cvt.u32.u64 %0, t; }" : "=r"(a) : "l"(p));
    return a;
}

// pack bf16x2: hi = bf16(f_odd), lo = bf16(f_even)
static __device__ __forceinline__ uint32_t pack2(float f_even, float f_odd) {
    uint32_t r;
    asm("cvt.rn.bf16x2.f32 %0, %1, %2;" : "=r"(r) : "f"(f_odd), "f"(f_even));
    return r;
}

#define MMA(D, A, B0, B1)                                                     \
    asm volatile(                                                             \
        "mma.sync.aligned.m16n8k16.row.col.f32.bf16.bf16.f32 "                \
        "{%0,%1,%2,%3},{%4,%5,%6,%7},{%8,%9},{%0,%1,%2,%3};"                  \
        : "+f"((D)[0]), "+f"((D)[1]), "+f"((D)[2]), "+f"((D)[3])              \
        : "r"((A)[0]), "r"((A)[1]), "r"((A)[2]), "r"((A)[3]), "r"(B0), "r"(B1))

#define LDS128(R, addr)                                                       \
    asm volatile("ld.shared.v4.b32 {%0,%1,%2,%3}, [%4];"                      \
                 : "=r"((R)[0]), "=r"((R)[1]), "=r"((R)[2]), "=r"((R)[3])     \
                 : "r"(addr))

static __device__ __forceinline__ void cp16(uint32_t sdst, const void* gsrc) {
    asm volatile("cp.async.cg.shared.global [%0], [%1], 16;"
                 :: "r"(sdst), "l"(gsrc) : "memory");
}

// ---------------------------------------------------------------------------
// Prep: split W into bf16 hi/mid and pack into mma A-fragment order.
// Index: ((t*4 + mb)*2 + s)*32 + lane, one uint4 each.
// ---------------------------------------------------------------------------
static __device__ __forceinline__ float split_res(float f, int s) {
    for (int i = 0; i < s; i++)
        f -= __bfloat162float(__float2bfloat16_rn(f));
    return f;
}

__global__ void prep_w_kernel(const float* __restrict__ W) {
    int idx = blockIdx.x * blockDim.x + threadIdx.x;
    if (idx >= NSTEP * FRAG_PER_STEP) return;
    int l = idx & 31;
    int r = idx >> 5;
    int s = r & 1;  r >>= 1;
    int mb = r & 3;
    int t = r >> 2;

    int q = l & 3;
    int row0 = mb * 16 + (l >> 2);
    int row1 = row0 + 8;
    int c = t * 16 + 2 * q;

    const float* w0 = W + (size_t)row0 * HIDDEN + c;
    const float* w1 = W + (size_t)row1 * HIDDEN + c;

    uint4 v;
    v.x = pack2(split_res(w0[0], s), split_res(w0[1], s));
    v.y = pack2(split_res(w1[0], s), split_res(w1[1], s));
    v.z = pack2(split_res(w0[8], s), split_res(w0[9], s));
    v.w = pack2(split_res(w1[8], s), split_res(w1[9], s));
    g_Wfrag[idx] = v;
}

__global__ void zero_flags_kernel() { g_flag_count = 0; }

// ---------------------------------------------------------------------------
// Main kernel
// ---------------------------------------------------------------------------
__global__ __launch_bounds__(THREADS, 1)
void gating_kernel(const float* __restrict__ x,
                   const float* __restrict__ bias,
                   float* __restrict__ out) {
    extern __shared__ char smem[];
    const uint32_t sb = s2u(smem);
    const int tid = threadIdx.x;
    const int w   = tid >> 5;
    const int l   = tid & 31;
    const int q   = l & 3;
    const int tg  = w & 7;     // token group: 16 tokens
    const int eh  = w >> 3;    // expert half: mblocks eh*2, eh*2+1

    auto issue_chunk = [&](int ch) {
        const char* gsrc = (const char*)g_Wfrag + (size_t)ch * CHUNK_BYTES;
        uint32_t sdst = sb + (ch % 3) * CHUNK_BYTES;
#pragma unroll
        for (int i = 0; i < CHUNK_BYTES / 16 / THREADS; i++) {
            int off = (tid + i * THREADS) * 16;
            cp16(sdst + off, gsrc + off);
        }
        asm volatile("cp.async.commit_group;" ::: "memory");
    };

    issue_chunk(0);
    issue_chunk(1);

    const int tbase = blockIdx.x * MTILE + tg * 16;
    const float* p0 = x + (size_t)(tbase + (l >> 2)) * HIDDEN + 2 * q;
    const float* p1 = p0 + (size_t)8 * HIDDEN;

    // x software pipeline: [slot][g][half] float2
    float2 vx[3][2][2];
#pragma unroll
    for (int d = 0; d < 3; d++) {
        vx[d][0][0] = *(const float2*)(p0 + d * 16);
        vx[d][0][1] = *(const float2*)(p0 + d * 16 + 8);
        vx[d][1][0] = *(const float2*)(p1 + d * 16);
        vx[d][1][1] = *(const float2*)(p1 + d * 16 + 8);
    }

    float D[2][2][4];
#pragma unroll
    for (int mb = 0; mb < 2; mb++)
#pragma unroll
        for (int g = 0; g < 2; g++)
#pragma unroll
            for (int i = 0; i < 4; i++) D[mb][g][i] = 0.0f;

#pragma unroll 1
    for (int t = 0; t < NSTEP; t++) {
        if ((t & (STEPS_PER_CHUNK - 1)) == 0) {
            const int ch = t / STEPS_PER_CHUNK;
            if (ch < NCHUNK - 1)
                asm volatile("cp.async.wait_group 1;" ::: "memory");
            else
                asm volatile("cp.async.wait_group 0;" ::: "memory");
            __syncthreads();
            if (ch + 2 < NCHUNK) issue_chunk(ch + 2);
        }

        const int slot = t % 3;

        // ---- A fragments: this warp's 2 mblocks x 2 splits ----
        const uint32_t base = sb + ((t / STEPS_PER_CHUNK) % 3) * CHUNK_BYTES
                              + (t & (STEPS_PER_CHUNK - 1)) * (FRAG_PER_STEP * 16)
                              + l * 16;
        uint32_t Af[2][2][4];
#pragma unroll
        for (int mb = 0; mb < 2; mb++) {
            const uint32_t mbase = base + (eh * 2 + mb) * 1024;
            LDS128(Af[mb][0], mbase);
            LDS128(Af[mb][1], mbase + 512);
        }

        // ---- B fragments: H and M splits ----
        uint32_t Bs[2][2][2];
#pragma unroll
        for (int g = 0; g < 2; g++) {
#pragma unroll
            for (int h = 0; h < 2; h++) {
                float f0 = vx[slot][g][h].x, f1 = vx[slot][g][h].y;
                uint32_t H = pack2(f0, f1);
                float h0 = __uint_as_float(H << 16);
                float h1 = __uint_as_float(H & 0xFFFF0000u);
                uint32_t M = pack2(f0 - h0, f1 - h1);
                Bs[0][g][h] = H; Bs[1][g][h] = M;
            }
        }

        // ---- prefetch x for step t+3 ----
        if (t + 3 < NSTEP) {
            const float* q0 = p0 + (size_t)(t + 3) * 16;
            const float* q1 = p1 + (size_t)(t + 3) * 16;
            vx[slot][0][0] = *(const float2*)(q0);
            vx[slot][0][1] = *(const float2*)(q0 + 8);
            vx[slot][1][0] = *(const float2*)(q1);
            vx[slot][1][1] = *(const float2*)(q1 + 8);
        }

        // ---- 12 MMA: HxH, HxM, MxH; 4 independent accumulators each ----
#define PRODUCT(sa, sbx)                                                      \
        MMA(D[0][0], Af[0][sa], Bs[sbx][0][0], Bs[sbx][0][1]);                \
        MMA(D[0][1], Af[0][sa], Bs[sbx][1][0], Bs[sbx][1][1]);                \
        MMA(D[1][0], Af[1][sa], Bs[sbx][0][0], Bs[sbx][0][1]);                \
        MMA(D[1][1], Af[1][sa], Bs[sbx][1][0], Bs[sbx][1][1]);

        PRODUCT(0, 0)   // HxH
        PRODUCT(0, 1)   // HxM
        PRODUCT(1, 0)   // MxH
#undef PRODUCT
    }

    // All warps must be done reading the smem ring before we overwrite it.
    __syncthreads();

    // ---- epilogue: stage logits in smem ----
    float* slog = (float*)smem;   // pitch 65 floats per token
#pragma unroll
    for (int mb = 0; mb < 2; mb++) {
        int e0 = (eh * 2 + mb) * 16 + (l >> 2);
        int e1 = e0 + 8;
#pragma unroll
        for (int g = 0; g < 2; g++) {
            int tk = tg * 16 + g * 8 + 2 * q;
            slog[(size_t)tk * 65 + e0]       = D[mb][g][0];
            slog[(size_t)(tk + 1) * 65 + e0] = D[mb][g][1];
            slog[(size_t)tk * 65 + e1]       = D[mb][g][2];
            slog[(size_t)(tk + 1) * 65 + e1] = D[mb][g][3];
        }
    }
    __syncthreads();

    if (tid < MTILE) {
        const float* row = slog + (size_t)tid * 65;
        float m1 = -3.4e38f, m2 = -3.4e38f, m3 = -3.4e38f;
        int i1 = 0, i2 = 0;
        float lg[NEXP];
#pragma unroll
        for (int e = 0; e < NEXP; e++) {
            float vv = row[e] + bias[e];
            lg[e] = vv;
            if (vv > m1)      { m3 = m2; m2 = m1; i2 = i1; m1 = vv; i1 = e; }
            else if (vv > m2) { m3 = m2; m2 = vv; i2 = e; }
            else if (vv > m3) { m3 = vv; }
        }
        float s = 0.0f;
#pragma unroll
        for (int e = 0; e < NEXP; e++) s += __expf(lg[e] - m1);

        const float v1 = 1.0f / s;
        const float v2 = __expf(m2 - m1) * v1;
        const int token = blockIdx.x * MTILE + tid;
        ((float2*)out)[token] = make_float2(v1, v2);
        ((float2*)(out + 2 * NTOK))[token] = make_float2((float)i1, (float)i2);

        // ambiguous ordering? -> flag for exact recompute
        if ((m1 - m2) < GAP_THR || (m2 - m3) < GAP_THR) {
            int slot = atomicAdd(&g_flag_count, 1);
            if (slot < NTOK) g_flag_tokens[slot] = token;
        }
    }
}

// ---------------------------------------------------------------------------
// Fixup: exact fp32 recompute of flagged tokens (deterministic correctness).
// ---------------------------------------------------------------------------
__global__ __launch_bounds__(256, 1)
void fixup_kernel(const float* __restrict__ x,
                  const float* __restrict__ W,
                  const float* __restrict__ bias,
                  float* __restrict__ out) {
    __shared__ float xs[HIDDEN];
    __shared__ float partial[256];
    __shared__ float lg[NEXP];
    const int tid = threadIdx.x;
    const int cnt = min(g_flag_count, NTOK);

    for (int i = blockIdx.x; i < cnt; i += gridDim.x) {
        const int tok = g_flag_tokens[i];
        for (int j = tid; j < HIDDEN / 4; j += 256)
            ((float4*)xs)[j] = ((const float4*)(x + (size_t)tok * HIDDEN))[j];
        __syncthreads();

        const int e = tid >> 2, p = tid & 3;
        const float* wr = W + (size_t)e * HIDDEN + p * 1024;
        const float* xr = xs + p * 1024;
        float s = 0.0f;
#pragma unroll 8
        for (int k = 0; k < 1024; k += 4) {
            float4 a = *(const float4*)(xr + k);
            float4 bb = *(const float4*)(wr + k);
            s += a.x * bb.x + a.y * bb.y + a.z * bb.z + a.w * bb.w;
        }
        partial[tid] = s;
        __syncthreads();
        if (p == 0)
            lg[e] = partial[tid] + partial[tid + 1] + partial[tid + 2]
                  + partial[tid + 3] + bias[e];
        __syncthreads();

        if (tid == 0) {
            float m1 = -3.4e38f, m2 = -3.4e38f;
            int i1 = 0, i2 = 0;
            for (int ee = 0; ee < NEXP; ee++) {
                float vv = lg[ee];
                if (vv > m1)      { m2 = m1; i2 = i1; m1 = vv; i1 = ee; }
                else if (vv > m2) { m2 = vv; i2 = ee; }
            }
            float ssum = 0.0f;
            for (int ee = 0; ee < NEXP; ee++) ssum += __expf(lg[ee] - m1);
            const float v1 = 1.0f / ssum;
            const float v2 = __expf(m2 - m1) * v1;
            ((float2*)out)[tok] = make_float2(v1, v2);
            ((float2*)(out + 2 * NTOK))[tok] = make_float2((float)i1, (float)i2);
        }
        __syncthreads();
    }
}

// ---------------------------------------------------------------------------
extern "C" void kernel_launch(void* const* d_in, const int* in_sizes, int n_in,
                              void* d_out, int out_size) {
    const float* x = (const float*)d_in[0];
    const float* W = (const float*)d_in[1];
    const float* b = (const float*)d_in[2];
    float* out = (float*)d_out;

    cudaFuncSetAttribute(gating_kernel, cudaFuncAttributeMaxDynamicSharedMemorySize,
                         SMEM_TOTAL);

    prep_w_kernel<<<(NSTEP * FRAG_PER_STEP + 255) / 256, 256>>>(W);
    zero_flags_kernel<<<1, 1>>>();
    gating_kernel<<<NCTA, THREADS, SMEM_TOTAL>>>(x, b, out);
    fixup_kernel<<<64, 256>>>(x, W, b, out);
}

// round 6
// speedup vs baseline: 1.3551x; 1.3551x over previous
#include <cuda_runtime.h>
#include <cuda_bf16.h>
#include <cstdint>

// ---------------------------------------------------------------------------
// GatingNetwork: logits = x @ W^T + b ; softmax ; top-2 (values, indices)
// 2-way bf16 split of both operands, 3 partial products (HH+HM+MH) on
// mma.sync m16n8k16 -> logit abs error ~3e-7. Tokens with ambiguous top-3
// ordering (gap < 1e-5) are recomputed exactly in fp32 by a parallel fixup.
// 256 threads/CTA: 8 warps, each owns 16 tokens x 64 experts (keeps L1
// x-load wavefronts at half the 512-thread variant's).
// ---------------------------------------------------------------------------

#define HIDDEN   4096
#define NEXP     64
#define NTOK     16384
#define MTILE    128
#define NCTA     (NTOK / MTILE)        // 128
#define THREADS  256
#define NSTEP    (HIDDEN / 16)         // 256 k16-steps
#define STEPS_PER_CHUNK 8              // K=128 per W chunk
#define NCHUNK   (NSTEP / STEPS_PER_CHUNK)  // 32
#define GAP_THR  1e-5f

// W fragment image: per k16 step: 4 mblocks x 2 splits x 32 lanes x uint4
#define FRAG_PER_STEP   (4 * 2 * 32)           // 256 uint4 = 4 KB
#define CHUNK_BYTES     (STEPS_PER_CHUNK * FRAG_PER_STEP * 16)  // 32768
#define SMEM_TOTAL      (3 * CHUNK_BYTES)      // 98304

__device__ uint4 g_Wfrag[NSTEP * FRAG_PER_STEP];   // 1 MB
__device__ int   g_flag_count;
__device__ int   g_flag_tokens[NTOK];

static __device__ __forceinline__ uint32_t s2u(const void* p) {
    uint32_t a;
    asm("{ .reg .u64 t; cvta.to.shared.u64 t, %1; cvt.u32.u64 %0, t; }" : "=r"(a) : "l"(p));
    return a;
}

// pack bf16x2: hi = bf16(f_odd), lo = bf16(f_even)
static __device__ __forceinline__ uint32_t pack2(float f_even, float f_odd) {
    uint32_t r;
    asm("cvt.rn.bf16x2.f32 %0, %1, %2;" : "=r"(r) : "f"(f_odd), "f"(f_even));
    return r;
}

#define MMA(D, A, B0, B1)                                                     \
    asm volatile(                                                             \
        "mma.sync.aligned.m16n8k16.row.col.f32.bf16.bf16.f32 "                \
        "{%0,%1,%2,%3},{%4,%5,%6,%7},{%8,%9},{%0,%1,%2,%3};"                  \
        : "+f"((D)[0]), "+f"((D)[1]), "+f"((D)[2]), "+f"((D)[3])              \
        : "r"((A)[0]), "r"((A)[1]), "r"((A)[2]), "r"((A)[3]), "r"(B0), "r"(B1))

#define LDS128(R, addr)                                                       \
    asm volatile("ld.shared.v4.b32 {%0,%1,%2,%3}, [%4];"                      \
                 : "=r"((R)[0]), "=r"((R)[1]), "=r"((R)[2]), "=r"((R)[3])     \
                 : "r"(addr))

static __device__ __forceinline__ void cp16(uint32_t sdst, const void* gsrc) {
    asm volatile("cp.async.cg.shared.global [%0], [%1], 16;"
                 :: "r"(sdst), "l"(gsrc) : "memory");
}

// ---------------------------------------------------------------------------
// Prep: split W into bf16 hi/mid and pack into mma A-fragment order.
// Index: ((t*4 + mb)*2 + s)*32 + lane, one uint4 each. Also zeroes flags.
// ---------------------------------------------------------------------------
static __device__ __forceinline__ float split_res(float f, int s) {
    for (int i = 0; i < s; i++)
        f -= __bfloat162float(__float2bfloat16_rn(f));
    return f;
}

__global__ void prep_w_kernel(const float* __restrict__ W) {
    int idx = blockIdx.x * blockDim.x + threadIdx.x;
    if (idx == 0) g_flag_count = 0;
    if (idx >= NSTEP * FRAG_PER_STEP) return;
    int l = idx & 31;
    int r = idx >> 5;
    int s = r & 1;  r >>= 1;
    int mb = r & 3;
    int t = r >> 2;

    int q = l & 3;
    int row0 = mb * 16 + (l >> 2);
    int row1 = row0 + 8;
    int c = t * 16 + 2 * q;

    const float* w0 = W + (size_t)row0 * HIDDEN + c;
    const float* w1 = W + (size_t)row1 * HIDDEN + c;

    uint4 v;
    v.x = pack2(split_res(w0[0], s), split_res(w0[1], s));
    v.y = pack2(split_res(w1[0], s), split_res(w1[1], s));
    v.z = pack2(split_res(w0[8], s), split_res(w0[9], s));
    v.w = pack2(split_res(w1[8], s), split_res(w1[9], s));
    g_Wfrag[idx] = v;
}

// ---------------------------------------------------------------------------
// Main kernel: 8 warps, warp w owns tokens [blk*128 + w*16, +16), all 64 experts.
// ---------------------------------------------------------------------------
__global__ __launch_bounds__(THREADS, 1)
void gating_kernel(const float* __restrict__ x,
                   const float* __restrict__ bias,
                   float* __restrict__ out) {
    extern __shared__ char smem[];
    const uint32_t sb = s2u(smem);
    const int tid = threadIdx.x;
    const int w   = tid >> 5;
    const int l   = tid & 31;
    const int q   = l & 3;

    auto issue_chunk = [&](int ch) {
        const char* gsrc = (const char*)g_Wfrag + (size_t)ch * CHUNK_BYTES;
        uint32_t sdst = sb + (ch % 3) * CHUNK_BYTES;
#pragma unroll
        for (int i = 0; i < CHUNK_BYTES / 16 / THREADS; i++) {
            int off = (tid + i * THREADS) * 16;
            cp16(sdst + off, gsrc + off);
        }
        asm volatile("cp.async.commit_group;" ::: "memory");
    };

    issue_chunk(0);
    issue_chunk(1);

    const int tbase = blockIdx.x * MTILE + w * 16;
    const float* p0 = x + (size_t)(tbase + (l >> 2)) * HIDDEN + 2 * q;
    const float* p1 = p0 + (size_t)8 * HIDDEN;

    // x software pipeline: [slot][g][half] float2
    float2 vx[3][2][2];
#pragma unroll
    for (int d = 0; d < 3; d++) {
        vx[d][0][0] = *(const float2*)(p0 + d * 16);
        vx[d][0][1] = *(const float2*)(p0 + d * 16 + 8);
        vx[d][1][0] = *(const float2*)(p1 + d * 16);
        vx[d][1][1] = *(const float2*)(p1 + d * 16 + 8);
    }

    float D[4][2][4];
#pragma unroll
    for (int mb = 0; mb < 4; mb++)
#pragma unroll
        for (int g = 0; g < 2; g++)
#pragma unroll
            for (int i = 0; i < 4; i++) D[mb][g][i] = 0.0f;

#pragma unroll 1
    for (int t = 0; t < NSTEP; t++) {
        if ((t & (STEPS_PER_CHUNK - 1)) == 0) {
            const int ch = t / STEPS_PER_CHUNK;
            if (ch < NCHUNK - 1)
                asm volatile("cp.async.wait_group 1;" ::: "memory");
            else
                asm volatile("cp.async.wait_group 0;" ::: "memory");
            __syncthreads();
            if (ch + 2 < NCHUNK) issue_chunk(ch + 2);
        }

        const int slot = t % 3;

        // ---- B fragments: H and M splits ----
        uint32_t Bs[2][2][2];
#pragma unroll
        for (int g = 0; g < 2; g++) {
#pragma unroll
            for (int h = 0; h < 2; h++) {
                float f0 = vx[slot][g][h].x, f1 = vx[slot][g][h].y;
                uint32_t H = pack2(f0, f1);
                float h0 = __uint_as_float(H << 16);
                float h1 = __uint_as_float(H & 0xFFFF0000u);
                uint32_t M = pack2(f0 - h0, f1 - h1);
                Bs[0][g][h] = H; Bs[1][g][h] = M;
            }
        }

        // ---- prefetch x for step t+3 ----
        if (t + 3 < NSTEP) {
            const float* q0 = p0 + (size_t)(t + 3) * 16;
            const float* q1 = p1 + (size_t)(t + 3) * 16;
            vx[slot][0][0] = *(const float2*)(q0);
            vx[slot][0][1] = *(const float2*)(q0 + 8);
            vx[slot][1][0] = *(const float2*)(q1);
            vx[slot][1][1] = *(const float2*)(q1 + 8);
        }

        // ---- 24 MMA over 4 mblocks: HxH, HxM, MxH each for g=0,1 ----
        const uint32_t base = sb + ((t / STEPS_PER_CHUNK) % 3) * CHUNK_BYTES
                              + (t & (STEPS_PER_CHUNK - 1)) * (FRAG_PER_STEP * 16)
                              + l * 16;
#pragma unroll
        for (int mb = 0; mb < 4; mb++) {
            uint32_t AH[4], AM[4];
            const uint32_t mbase = base + mb * 1024;
            LDS128(AH, mbase);
            LDS128(AM, mbase + 512);
            MMA(D[mb][0], AH, Bs[0][0][0], Bs[0][0][1]);   // HxH g0
            MMA(D[mb][1], AH, Bs[0][1][0], Bs[0][1][1]);   // HxH g1
            MMA(D[mb][0], AH, Bs[1][0][0], Bs[1][0][1]);   // HxM g0
            MMA(D[mb][1], AH, Bs[1][1][0], Bs[1][1][1]);   // HxM g1
            MMA(D[mb][0], AM, Bs[0][0][0], Bs[0][0][1]);   // MxH g0
            MMA(D[mb][1], AM, Bs[0][1][0], Bs[0][1][1]);   // MxH g1
        }
    }

    // All warps must be done reading the smem ring before slog overwrites it.
    __syncthreads();

    // ---- epilogue: stage logits in smem ----
    float* slog = (float*)smem;   // pitch 65 floats per token
#pragma unroll
    for (int mb = 0; mb < 4; mb++) {
        int e0 = mb * 16 + (l >> 2);
        int e1 = e0 + 8;
#pragma unroll
        for (int g = 0; g < 2; g++) {
            int tk = w * 16 + g * 8 + 2 * q;
            slog[(size_t)tk * 65 + e0]       = D[mb][g][0];
            slog[(size_t)(tk + 1) * 65 + e0] = D[mb][g][1];
            slog[(size_t)tk * 65 + e1]       = D[mb][g][2];
            slog[(size_t)(tk + 1) * 65 + e1] = D[mb][g][3];
        }
    }
    __syncthreads();

    if (tid < MTILE) {
        const float* row = slog + (size_t)tid * 65;
        float m1 = -3.4e38f, m2 = -3.4e38f, m3 = -3.4e38f;
        int i1 = 0, i2 = 0;
        float lg[NEXP];
#pragma unroll
        for (int e = 0; e < NEXP; e++) {
            float vv = row[e] + bias[e];
            lg[e] = vv;
            if (vv > m1)      { m3 = m2; m2 = m1; i2 = i1; m1 = vv; i1 = e; }
            else if (vv > m2) { m3 = m2; m2 = vv; i2 = e; }
            else if (vv > m3) { m3 = vv; }
        }
        float s = 0.0f;
#pragma unroll
        for (int e = 0; e < NEXP; e++) s += __expf(lg[e] - m1);

        const float v1 = 1.0f / s;
        const float v2 = __expf(m2 - m1) * v1;
        const int token = blockIdx.x * MTILE + tid;
        ((float2*)out)[token] = make_float2(v1, v2);
        ((float2*)(out + 2 * NTOK))[token] = make_float2((float)i1, (float)i2);

        if ((m1 - m2) < GAP_THR || (m2 - m3) < GAP_THR) {
            int slot = atomicAdd(&g_flag_count, 1);
            if (slot < NTOK) g_flag_tokens[slot] = token;
        }
    }
}

// ---------------------------------------------------------------------------
// Fixup: exact fp32 recompute of flagged tokens. 8 warps, warp w -> experts
// w*8..w*8+7, lane-strided float4 dot + shuffle reduction. W stays L2-hot.
// ---------------------------------------------------------------------------
__global__ __launch_bounds__(256, 1)
void fixup_kernel(const float* __restrict__ x,
                  const float* __restrict__ W,
                  const float* __restrict__ bias,
                  float* __restrict__ out) {
    __shared__ float xs[HIDDEN];
    __shared__ float lg[NEXP];
    const int tid = threadIdx.x;
    const int w = tid >> 5, l = tid & 31;
    const int cnt = min(g_flag_count, NTOK);

    for (int i = blockIdx.x; i < cnt; i += gridDim.x) {
        const int tok = g_flag_tokens[i];
        __syncthreads();
        for (int j = tid; j < HIDDEN / 4; j += 256)
            ((float4*)xs)[j] = ((const float4*)(x + (size_t)tok * HIDDEN))[j];
        __syncthreads();

#pragma unroll
        for (int e8 = 0; e8 < 8; e8++) {
            const int e = w * 8 + e8;
            const float* wr = W + (size_t)e * HIDDEN;
            float s = 0.0f;
#pragma unroll 8
            for (int k = l * 4; k < HIDDEN; k += 128) {
                float4 a = *(const float4*)(xs + k);
                float4 bb = *(const float4*)(wr + k);
                s += a.x * bb.x + a.y * bb.y + a.z * bb.z + a.w * bb.w;
            }
#pragma unroll
            for (int o = 16; o; o >>= 1) s += __shfl_xor_sync(0xFFFFFFFFu, s, o);
            if (l == 0) lg[e] = s + bias[e];
        }
        __syncthreads();

        if (tid == 0) {
            float m1 = -3.4e38f, m2 = -3.4e38f;
            int i1 = 0, i2 = 0;
            for (int ee = 0; ee < NEXP; ee++) {
                float vv = lg[ee];
                if (vv > m1)      { m2 = m1; i2 = i1; m1 = vv; i1 = ee; }
                else if (vv > m2) { m2 = vv; i2 = ee; }
            }
            float ssum = 0.0f;
            for (int ee = 0; ee < NEXP; ee++) ssum += __expf(lg[ee] - m1);
            const float v1 = 1.0f / ssum;
            const float v2 = __expf(m2 - m1) * v1;
            ((float2*)out)[tok] = make_float2(v1, v2);
            ((float2*)(out + 2 * NTOK))[tok] = make_float2((float)i1, (float)i2);
        }
    }
}

// ---------------------------------------------------------------------------
extern "C" void kernel_launch(void* const* d_in, const int* in_sizes, int n_in,
                              void* d_out, int out_size) {
    const float* x = (const float*)d_in[0];
    const float* W = (const float*)d_in[1];
    const float* b = (const float*)d_in[2];
    float* out = (float*)d_out;

    cudaFuncSetAttribute(gating_kernel, cudaFuncAttributeMaxDynamicSharedMemorySize,
                         SMEM_TOTAL);

    prep_w_kernel<<<(NSTEP * FRAG_PER_STEP + 255) / 256, 256>>>(W);
    gating_kernel<<<NCTA, THREADS, SMEM_TOTAL>>>(x, b, out);
    fixup_kernel<<<128, 256>>>(x, W, b, out);
}